// round 1
// baseline (speedup 1.0000x reference)
#include <cuda_runtime.h>

// Problem constants
#define T_LEN 1024
#define B_SZ 2
#define E_DIM 1024
#define H_NUM 16
#define D_DIM 64
#define TB (T_LEN * B_SZ)          // 2048
#define CH 128                     // chunk length
#define NC (T_LEN / CH)            // 8 chunks
#define BHN (B_SZ * H_NUM)         // 32 head-batches
#define SCALE_ATT 0.125f           // 1/sqrt(64)

// Scratch (device globals; no allocation allowed)
__device__ float g_q[BHN * T_LEN * D_DIM];     // (b,h,t,d)
__device__ float g_k[BHN * T_LEN * D_DIM];
__device__ float g_v[BHN * T_LEN * D_DIM];
__device__ float g_attn[TB * E_DIM];           // (t,b,e)
__device__ float g_kvc[BHN * NC * D_DIM * D_DIM];   // per-chunk K^T V
__device__ float g_ssum[BHN * NC * D_DIM * D_DIM];  // exclusive prefix

// ---------------------------------------------------------------------------
// Input projection: for z in {q,k,v}:  out = X @ W_z^T + b_z, scattered into
// (b,h,t,d) layout. X is (TB, E) row-major with row m = t*B + b.
// Classic 128x128x8 SGEMM, 256 threads, 8x8 per-thread micro-tile.
// ---------------------------------------------------------------------------
__global__ __launch_bounds__(256, 2) void inproj_kernel(
    const float* __restrict__ q_in, const float* __restrict__ k_in,
    const float* __restrict__ v_in, const float* __restrict__ W,
    const float* __restrict__ bias)
{
    __shared__ float As[8][128];
    __shared__ float Bs[8][128];

    const int z = blockIdx.z;
    const float* A  = (z == 0) ? q_in : ((z == 1) ? k_in : v_in);
    const float* Wz = W + z * E_DIM * E_DIM;
    const float* bz = bias + z * E_DIM;

    const int tid = threadIdx.x;
    const int tx = tid & 15, ty = tid >> 4;
    const int m0 = blockIdx.y * 128, n0 = blockIdx.x * 128;
    const int lrow = tid >> 1;
    const int lk4  = (tid & 1) << 2;

    const float* Aptr = A  + (m0 + lrow) * E_DIM + lk4;
    const float* Bptr = Wz + (n0 + lrow) * E_DIM + lk4;

    float acc[8][8];
    #pragma unroll
    for (int i = 0; i < 8; ++i)
        #pragma unroll
        for (int j = 0; j < 8; ++j) acc[i][j] = 0.f;

    for (int k0 = 0; k0 < E_DIM; k0 += 8) {
        float4 a4 = *(const float4*)(Aptr + k0);
        float4 b4 = *(const float4*)(Bptr + k0);
        __syncthreads();
        As[lk4 + 0][lrow] = a4.x; As[lk4 + 1][lrow] = a4.y;
        As[lk4 + 2][lrow] = a4.z; As[lk4 + 3][lrow] = a4.w;
        Bs[lk4 + 0][lrow] = b4.x; Bs[lk4 + 1][lrow] = b4.y;
        Bs[lk4 + 2][lrow] = b4.z; Bs[lk4 + 3][lrow] = b4.w;
        __syncthreads();
        #pragma unroll
        for (int kk = 0; kk < 8; ++kk) {
            float af[8], bf[8];
            #pragma unroll
            for (int i = 0; i < 8; ++i) af[i] = As[kk][ty * 8 + i];
            #pragma unroll
            for (int j = 0; j < 8; ++j) bf[j] = Bs[kk][tx * 8 + j];
            #pragma unroll
            for (int i = 0; i < 8; ++i)
                #pragma unroll
                for (int j = 0; j < 8; ++j)
                    acc[i][j] = fmaf(af[i], bf[j], acc[i][j]);
        }
    }

    float* outb = (z == 0) ? g_q : ((z == 1) ? g_k : g_v);
    #pragma unroll
    for (int i = 0; i < 8; ++i) {
        const int m = m0 + ty * 8 + i;
        const int t = m >> 1, b = m & 1;
        #pragma unroll
        for (int j = 0; j < 8; ++j) {
            const int n = n0 + tx * 8 + j;
            const int h = n >> 6, d = n & 63;
            outb[((b * H_NUM + h) * T_LEN + t) * D_DIM + d] = acc[i][j] + bz[n];
        }
    }
}

// ---------------------------------------------------------------------------
// Output projection: out = attn @ Wo^T + bo. Same SGEMM structure.
// ---------------------------------------------------------------------------
__global__ __launch_bounds__(256, 2) void outproj_kernel(
    const float* __restrict__ W, const float* __restrict__ bias,
    float* __restrict__ out)
{
    __shared__ float As[8][128];
    __shared__ float Bs[8][128];

    const int tid = threadIdx.x;
    const int tx = tid & 15, ty = tid >> 4;
    const int m0 = blockIdx.y * 128, n0 = blockIdx.x * 128;
    const int lrow = tid >> 1;
    const int lk4  = (tid & 1) << 2;

    const float* Aptr = g_attn + (m0 + lrow) * E_DIM + lk4;
    const float* Bptr = W      + (n0 + lrow) * E_DIM + lk4;

    float acc[8][8];
    #pragma unroll
    for (int i = 0; i < 8; ++i)
        #pragma unroll
        for (int j = 0; j < 8; ++j) acc[i][j] = 0.f;

    for (int k0 = 0; k0 < E_DIM; k0 += 8) {
        float4 a4 = *(const float4*)(Aptr + k0);
        float4 b4 = *(const float4*)(Bptr + k0);
        __syncthreads();
        As[lk4 + 0][lrow] = a4.x; As[lk4 + 1][lrow] = a4.y;
        As[lk4 + 2][lrow] = a4.z; As[lk4 + 3][lrow] = a4.w;
        Bs[lk4 + 0][lrow] = b4.x; Bs[lk4 + 1][lrow] = b4.y;
        Bs[lk4 + 2][lrow] = b4.z; Bs[lk4 + 3][lrow] = b4.w;
        __syncthreads();
        #pragma unroll
        for (int kk = 0; kk < 8; ++kk) {
            float af[8], bf[8];
            #pragma unroll
            for (int i = 0; i < 8; ++i) af[i] = As[kk][ty * 8 + i];
            #pragma unroll
            for (int j = 0; j < 8; ++j) bf[j] = Bs[kk][tx * 8 + j];
            #pragma unroll
            for (int i = 0; i < 8; ++i)
                #pragma unroll
                for (int j = 0; j < 8; ++j)
                    acc[i][j] = fmaf(af[i], bf[j], acc[i][j]);
        }
    }

    #pragma unroll
    for (int i = 0; i < 8; ++i) {
        const int m = m0 + ty * 8 + i;
        #pragma unroll
        for (int j = 0; j < 8; ++j) {
            const int n = n0 + tx * 8 + j;
            out[m * E_DIM + n] = acc[i][j] + bias[n];
        }
    }
}

// ---------------------------------------------------------------------------
// Pass A: per (head, chunk) compute KV_c = K_c^T V_c  (64x64, depth 128)
// ---------------------------------------------------------------------------
__global__ __launch_bounds__(256) void kvchunk_kernel()
{
    const int c = blockIdx.x, bh = blockIdx.y;
    const float* Kg = g_k + (bh * T_LEN + c * CH) * D_DIM;
    const float* Vg = g_v + (bh * T_LEN + c * CH) * D_DIM;
    __shared__ float Ks[32 * 64];
    __shared__ float Vs[32 * 64];
    const int tid = threadIdx.x;
    const int tx = tid & 15, ty = tid >> 4;

    float acc[4][4];
    #pragma unroll
    for (int i = 0; i < 4; ++i)
        #pragma unroll
        for (int j = 0; j < 4; ++j) acc[i][j] = 0.f;

    for (int s0 = 0; s0 < CH; s0 += 32) {
        __syncthreads();
        #pragma unroll
        for (int u = 0; u < 2; ++u) {
            const int idx = tid * 4 + u * 1024;
            *(float4*)&Ks[idx] = *(const float4*)&Kg[s0 * 64 + idx];
            *(float4*)&Vs[idx] = *(const float4*)&Vg[s0 * 64 + idx];
        }
        __syncthreads();
        #pragma unroll 8
        for (int ss = 0; ss < 32; ++ss) {
            float kf[4], vf[4];
            #pragma unroll
            for (int i = 0; i < 4; ++i) kf[i] = Ks[ss * 64 + ty * 4 + i];
            #pragma unroll
            for (int j = 0; j < 4; ++j) vf[j] = Vs[ss * 64 + tx * 4 + j];
            #pragma unroll
            for (int i = 0; i < 4; ++i)
                #pragma unroll
                for (int j = 0; j < 4; ++j)
                    acc[i][j] = fmaf(kf[i], vf[j], acc[i][j]);
        }
    }

    float* outp = g_kvc + (bh * NC + c) * D_DIM * D_DIM;
    #pragma unroll
    for (int i = 0; i < 4; ++i)
        #pragma unroll
        for (int j = 0; j < 4; ++j)
            outp[(ty * 4 + i) * 64 + tx * 4 + j] = acc[i][j];
}

// ---------------------------------------------------------------------------
// Pass B: exclusive prefix-sum of chunk KV states over the 8 chunks
// ---------------------------------------------------------------------------
__global__ __launch_bounds__(256) void scan_kernel()
{
    const int bh = blockIdx.x;
    for (int e = threadIdx.x; e < D_DIM * D_DIM; e += 256) {
        float s = 0.f;
        #pragma unroll
        for (int c = 0; c < NC; ++c) {
            g_ssum[(bh * NC + c) * D_DIM * D_DIM + e] = s;
            s += g_kvc[(bh * NC + c) * D_DIM * D_DIM + e];
        }
    }
}

// ---------------------------------------------------------------------------
// Pass C: per (head, chunk): O_c = (Q_c @ S_c + tril(Q_c K_c^T) @ V_c) * scale
// smem: Q(128x65), K(128x65), V(128x64), S(64x64), P(128x128) = 177 KB
// ---------------------------------------------------------------------------
#define SMEM_C_FLOATS (128 * 65 + 128 * 65 + 128 * 64 + 64 * 64 + 128 * 128)
#define SMEM_C_BYTES (SMEM_C_FLOATS * 4)

__global__ __launch_bounds__(256) void attn_kernel()
{
    extern __shared__ float sm[];
    float* Qs = sm;                    // 128 x 65 (padded)
    float* Ks = Qs + 128 * 65;         // 128 x 65 (padded)
    float* Vs = Ks + 128 * 65;         // 128 x 64
    float* Ss = Vs + 128 * 64;         // 64 x 64
    float* Ps = Ss + 64 * 64;          // 128 x 128

    const int c = blockIdx.x, bh = blockIdx.y;
    const int tid = threadIdx.x;
    const float* Qg = g_q + (bh * T_LEN + c * CH) * D_DIM;
    const float* Kg = g_k + (bh * T_LEN + c * CH) * D_DIM;
    const float* Vg = g_v + (bh * T_LEN + c * CH) * D_DIM;
    const float* Sg = g_ssum + (bh * NC + c) * D_DIM * D_DIM;

    // Load tiles
    for (int idx = tid * 4; idx < CH * D_DIM; idx += 256 * 4) {
        const int row = idx >> 6, col = idx & 63;
        float4 q4 = *(const float4*)&Qg[idx];
        float4 k4 = *(const float4*)&Kg[idx];
        *(float4*)&Vs[idx] = *(const float4*)&Vg[idx];
        Qs[row * 65 + col + 0] = q4.x; Qs[row * 65 + col + 1] = q4.y;
        Qs[row * 65 + col + 2] = q4.z; Qs[row * 65 + col + 3] = q4.w;
        Ks[row * 65 + col + 0] = k4.x; Ks[row * 65 + col + 1] = k4.y;
        Ks[row * 65 + col + 2] = k4.z; Ks[row * 65 + col + 3] = k4.w;
    }
    for (int idx = tid * 4; idx < D_DIM * D_DIM; idx += 256 * 4)
        *(float4*)&Ss[idx] = *(const float4*)&Sg[idx];
    __syncthreads();

    const int tx = tid & 15, ty = tid >> 4;

    // P = tril(Q K^T), 128x128, 64 per-thread outputs (8x8)
    {
        float p[8][8];
        #pragma unroll
        for (int i = 0; i < 8; ++i)
            #pragma unroll
            for (int j = 0; j < 8; ++j) p[i][j] = 0.f;

        #pragma unroll 4
        for (int d = 0; d < D_DIM; ++d) {
            float qf[8], kf[8];
            #pragma unroll
            for (int i = 0; i < 8; ++i) qf[i] = Qs[(ty * 8 + i) * 65 + d];
            #pragma unroll
            for (int j = 0; j < 8; ++j) kf[j] = Ks[(tx * 8 + j) * 65 + d];
            #pragma unroll
            for (int i = 0; i < 8; ++i)
                #pragma unroll
                for (int j = 0; j < 8; ++j)
                    p[i][j] = fmaf(qf[i], kf[j], p[i][j]);
        }
        #pragma unroll
        for (int i = 0; i < 8; ++i) {
            const int i_ = ty * 8 + i;
            #pragma unroll
            for (int j = 0; j < 8; ++j) {
                const int j_ = tx * 8 + j;
                Ps[i_ * 128 + j_] = (j_ <= i_) ? p[i][j] : 0.f;
            }
        }
    }
    __syncthreads();

    // O = Q @ S + P @ V, 128x64, 32 per-thread outputs (8 rows x 4 cols)
    {
        const int v0 = tx * 4;
        const int i0 = ty * 8;
        float o[8][4];
        #pragma unroll
        for (int i = 0; i < 8; ++i)
            #pragma unroll
            for (int j = 0; j < 4; ++j) o[i][j] = 0.f;

        #pragma unroll 4
        for (int k = 0; k < D_DIM; ++k) {
            float sf[4];
            #pragma unroll
            for (int j = 0; j < 4; ++j) sf[j] = Ss[k * 64 + v0 + j];
            #pragma unroll
            for (int i = 0; i < 8; ++i) {
                const float q = Qs[(i0 + i) * 65 + k];
                #pragma unroll
                for (int j = 0; j < 4; ++j) o[i][j] = fmaf(q, sf[j], o[i][j]);
            }
        }
        #pragma unroll 4
        for (int j2 = 0; j2 < CH; ++j2) {
            float vf[4];
            #pragma unroll
            for (int j = 0; j < 4; ++j) vf[j] = Vs[j2 * 64 + v0 + j];
            #pragma unroll
            for (int i = 0; i < 8; ++i) {
                const float pp = Ps[(i0 + i) * 128 + j2];
                #pragma unroll
                for (int j = 0; j < 4; ++j) o[i][j] = fmaf(pp, vf[j], o[i][j]);
            }
        }

        const int b = bh / H_NUM, h = bh % H_NUM;
        #pragma unroll
        for (int i = 0; i < 8; ++i) {
            const int t = c * CH + i0 + i;
            float* dst = g_attn + (t * B_SZ + b) * E_DIM + h * D_DIM + v0;
            #pragma unroll
            for (int j = 0; j < 4; ++j) dst[j] = o[i][j] * SCALE_ATT;
        }
    }
}

// ---------------------------------------------------------------------------
extern "C" void kernel_launch(void* const* d_in, const int* in_sizes, int n_in,
                              void* d_out, int out_size)
{
    (void)in_sizes; (void)n_in; (void)out_size;
    const float* query = (const float*)d_in[0];
    const float* key_  = (const float*)d_in[1];
    const float* value = (const float*)d_in[2];
    const float* ipw   = (const float*)d_in[3];
    const float* ipb   = (const float*)d_in[4];
    const float* opw   = (const float*)d_in[5];
    const float* opb   = (const float*)d_in[6];
    float* out = (float*)d_out;

    cudaFuncSetAttribute(attn_kernel,
                         cudaFuncAttributeMaxDynamicSharedMemorySize,
                         SMEM_C_BYTES);

    dim3 g1(E_DIM / 128, TB / 128, 3);
    inproj_kernel<<<g1, 256>>>(query, key_, value, ipw, ipb);

    kvchunk_kernel<<<dim3(NC, BHN), 256>>>();
    scan_kernel<<<BHN, 256>>>();
    attn_kernel<<<dim3(NC, BHN), 256, SMEM_C_BYTES>>>();

    dim3 g2(E_DIM / 128, TB / 128);
    outproj_kernel<<<g2, 256>>>(opw, opb, out);
}